// round 2
// baseline (speedup 1.0000x reference)
#include <cuda_runtime.h>
#include <stdint.h>

// ProbabilisticPrediction: compute categorical idx via Gumbel-argmax (JAX
// threefry, partitionable), then evaluate the 3-layer MLP only at the 1024
// selected (b,q,idx) points. R2: break FMA dependency chains with multiple
// accumulators, parallelize layer3 across all threads, shuffle-based argmax.

#define B_   4
#define QL_  256
#define CL_  512
#define XD_  128
#define ED_  128
#define DIM_ 128
#define YD_  16

// ---------------------------------------------------------------- threefry2x32
__host__ __device__ inline void tf2x32(uint32_t k0, uint32_t k1,
                                       uint32_t c0, uint32_t c1,
                                       uint32_t& o0, uint32_t& o1) {
    uint32_t k2 = k0 ^ k1 ^ 0x1BD11BDAu;
    uint32_t x0 = c0 + k0, x1 = c1 + k1;
#define TFR(d) do { x0 += x1; x1 = (x1 << (d)) | (x1 >> (32 - (d))); x1 ^= x0; } while (0)
    TFR(13); TFR(15); TFR(26); TFR(6);   x0 += k1; x1 += k2 + 1u;
    TFR(17); TFR(29); TFR(16); TFR(24);  x0 += k2; x1 += k0 + 2u;
    TFR(13); TFR(15); TFR(26); TFR(6);   x0 += k0; x1 += k1 + 3u;
    TFR(17); TFR(29); TFR(16); TFR(24);  x0 += k1; x1 += k2 + 4u;
    TFR(13); TFR(15); TFR(26); TFR(6);   x0 += k2; x1 += k0 + 5u;
#undef TFR
    o0 = x0; o1 = x1;
}

__device__ inline uint32_t jax_bits(uint32_t k0, uint32_t k1, uint32_t j) {
    uint32_t o0, o1;
    tf2x32(k0, k1, 0u, j, o0, o1);   // partitionable: 64-bit iota (0, j)
    return o0 ^ o1;
}

__device__ inline float bits_to_unit(uint32_t b) {      // [0, 1)
    return __uint_as_float((b >> 9) | 0x3f800000u) - 1.0f;
}

// XLA ErfInv32 (Giles) -- matches jax.random.normal exactly.
__device__ inline float erfinv_xla(float x) {
    float w = -log1pf(-x * x);
    float p;
    if (w < 5.0f) {
        w -= 2.5f;
        p =            2.81022636e-08f;
        p = fmaf(p, w, 3.43273939e-07f);
        p = fmaf(p, w, -3.5233877e-06f);
        p = fmaf(p, w, -4.39150654e-06f);
        p = fmaf(p, w, 0.00021858087f);
        p = fmaf(p, w, -0.00125372503f);
        p = fmaf(p, w, -0.00417768164f);
        p = fmaf(p, w, 0.246640727f);
        p = fmaf(p, w, 1.50140941f);
    } else {
        w = sqrtf(w) - 3.0f;
        p =            -0.000200214257f;
        p = fmaf(p, w, 0.000100950558f);
        p = fmaf(p, w, 0.00134934322f);
        p = fmaf(p, w, -0.00367342844f);
        p = fmaf(p, w, 0.00573950773f);
        p = fmaf(p, w, -0.0076224613f);
        p = fmaf(p, w, 0.00943887047f);
        p = fmaf(p, w, 1.00167406f);
        p = fmaf(p, w, 2.83297682f);
    }
    return p * x;
}

// ---------------------------------------------------------------------- kernel
__global__ __launch_bounds__(128)
void pp_fused_kernel(const float* __restrict__ q,
                     const float* __restrict__ f_embed,
                     const float* __restrict__ att_logits,
                     const float* __restrict__ W1q,
                     const float* __restrict__ W1f,
                     const float* __restrict__ b1,
                     const float* __restrict__ W2,
                     const float* __restrict__ b2,
                     const float* __restrict__ Wout,
                     const float* __restrict__ bout,
                     float* __restrict__ out,
                     uint32_t kc0, uint32_t kc1,   // categorical key
                     uint32_t ke0, uint32_t ke1)   // eps key
{
    const int t  = threadIdx.x;          // 0..127
    const int w  = t >> 5;               // warp 0..3
    const int ln = t & 31;
    const int bq = blockIdx.x;           // b*QL + ql
    const int b  = bq >> 8;

    __shared__ float sQ[DIM_];
    __shared__ float sB[DIM_];
    __shared__ float sH[DIM_];
    __shared__ float sP[4][2 * YD_];
    __shared__ float sO[2 * YD_];
    __shared__ float sV[4];
    __shared__ int   sIw[4];
    __shared__ int   sIdx;

    // Prefetch q row early (DRAM latency hides under threefry compute).
    sQ[t] = q[(size_t)bq * XD_ + t];

    // ---------------- Phase 1: idx = argmax_c (gumbel + logits) -------------
    const float TINY = 1.17549435e-38f;
    float best = -__int_as_float(0x7f800000);
    int bi = 0;
    const float* lrow = att_logits + (size_t)bq * CL_;
#pragma unroll
    for (int k = 0; k < CL_ / 128; ++k) {
        int c = t + k * 128;
        uint32_t j = (uint32_t)bq * (uint32_t)CL_ + (uint32_t)c;
        float u = bits_to_unit(jax_bits(kc0, kc1, j));
        u = fmaxf(TINY, u * (1.0f - TINY) + TINY);
        float g = -logf(-logf(u));
        float v = g + lrow[c];
        if (v > best || (v == best && c < bi)) { best = v; bi = c; }
    }
    // warp-level argmax (first-index tiebreak)
#pragma unroll
    for (int off = 16; off; off >>= 1) {
        float v2 = __shfl_xor_sync(0xffffffffu, best, off);
        int   i2 = __shfl_xor_sync(0xffffffffu, bi,   off);
        if (v2 > best || (v2 == best && i2 < bi)) { best = v2; bi = i2; }
    }
    if (ln == 0) { sV[w] = best; sIw[w] = bi; }
    __syncthreads();
    if (t == 0) {
        float bv = sV[0]; int bj = sIw[0];
#pragma unroll
        for (int k = 1; k < 4; ++k) {
            if (sV[k] > bv || (sV[k] == bv && sIw[k] < bj)) { bv = sV[k]; bj = sIw[k]; }
        }
        sIdx = bj;
    }
    __syncthreads();
    const int idx = sIdx;

    // ---------------- Phase 2: fused MLP at the selected component ----------
    sB[t] = f_embed[((size_t)b * CL_ + idx) * ED_ + t];    // selected f row
    __syncthreads();

    // Layer 1: h = relu(q@W1q + f@W1f + b1)  -- 8 independent FMA chains
    {
        float aq0 = 0.f, aq1 = 0.f, aq2 = 0.f, aq3 = 0.f;
        float af0 = 0.f, af1 = 0.f, af2 = 0.f, af3 = 0.f;
#pragma unroll 4
        for (int d = 0; d < DIM_; d += 4) {
            aq0 = fmaf(sQ[d + 0], W1q[(d + 0) * DIM_ + t], aq0);
            aq1 = fmaf(sQ[d + 1], W1q[(d + 1) * DIM_ + t], aq1);
            aq2 = fmaf(sQ[d + 2], W1q[(d + 2) * DIM_ + t], aq2);
            aq3 = fmaf(sQ[d + 3], W1q[(d + 3) * DIM_ + t], aq3);
            af0 = fmaf(sB[d + 0], W1f[(d + 0) * DIM_ + t], af0);
            af1 = fmaf(sB[d + 1], W1f[(d + 1) * DIM_ + t], af1);
            af2 = fmaf(sB[d + 2], W1f[(d + 2) * DIM_ + t], af2);
            af3 = fmaf(sB[d + 3], W1f[(d + 3) * DIM_ + t], af3);
        }
        float acc = b1[t] + ((aq0 + aq1) + (aq2 + aq3)) + ((af0 + af1) + (af2 + af3));
        sH[t] = fmaxf(acc, 0.0f);
    }
    __syncthreads();

    // Layer 2: h2 = relu(h@W2 + b2) -- 4 independent chains
    {
        float a0 = 0.f, a1 = 0.f, a2 = 0.f, a3 = 0.f;
#pragma unroll 4
        for (int d = 0; d < DIM_; d += 4) {
            a0 = fmaf(sH[d + 0], W2[(d + 0) * DIM_ + t], a0);
            a1 = fmaf(sH[d + 1], W2[(d + 1) * DIM_ + t], a1);
            a2 = fmaf(sH[d + 2], W2[(d + 2) * DIM_ + t], a2);
            a3 = fmaf(sH[d + 3], W2[(d + 3) * DIM_ + t], a3);
        }
        sQ[t] = fmaxf(b2[t] + ((a0 + a1) + (a2 + a3)), 0.0f);   // reuse sQ as h2
    }
    __syncthreads();

    // Layer 3: out = h2@Wout + bout -- all 128 threads: (o = t&31, p = t>>5)
    {
        const int o = ln;                 // output column 0..31
        const int p = w;                  // d-quarter 0..3
        const int d0 = p * 32;
        float a0 = 0.f, a1 = 0.f;
#pragma unroll
        for (int d = 0; d < 32; d += 2) {
            a0 = fmaf(sQ[d0 + d],     Wout[(d0 + d)     * (2 * YD_) + o], a0);
            a1 = fmaf(sQ[d0 + d + 1], Wout[(d0 + d + 1) * (2 * YD_) + o], a1);
        }
        sP[p][o] = a0 + a1;
    }
    __syncthreads();

    if (t < 2 * YD_) {
        sO[t] = bout[t] + ((sP[0][t] + sP[1][t]) + (sP[2][t] + sP[3][t]));
    }
    __syncthreads();

    if (t < YD_) {
        uint32_t m = (uint32_t)bq * (uint32_t)YD_ + (uint32_t)t;
        float u = bits_to_unit(jax_bits(ke0, ke1, m));
        const float lo = -0.99999994f;
        float x = fmaxf(lo, u * (1.0f - lo) + lo);
        float eps = 1.41421356237f * erfinv_xla(x);
        float s = fmaxf(-15.0f, sO[YD_ + t]);
        float sigma = fmaxf(s, 0.0f) + log1pf(expf(-fabsf(s)));   // softplus
        out[(size_t)bq * YD_ + t] = fmaf(sigma, eps, sO[t]);
    }
}

// ---------------------------------------------------------------------- launch
extern "C" void kernel_launch(void* const* d_in, const int* in_sizes, int n_in,
                              void* d_out, int out_size) {
    const float* q     = (const float*)d_in[0];
    const float* f_emb = (const float*)d_in[1];
    const float* alog  = (const float*)d_in[2];
    const float* W1q   = (const float*)d_in[3];
    const float* W1f   = (const float*)d_in[4];
    const float* b1    = (const float*)d_in[5];
    const float* W2    = (const float*)d_in[6];
    const float* b2    = (const float*)d_in[7];
    const float* Wout  = (const float*)d_in[8];
    const float* bout  = (const float*)d_in[9];
    float* out = (float*)d_out;

    // split(jax.random.key(1), 2), partitionable: subkey_i = tf(key, (0, i))
    uint32_t kc0, kc1, ke0, ke1;
    tf2x32(0u, 1u, 0u, 0u, kc0, kc1);
    tf2x32(0u, 1u, 0u, 1u, ke0, ke1);

    pp_fused_kernel<<<B_ * QL_, 128>>>(q, f_emb, alog, W1q, W1f, b1, W2, b2,
                                       Wout, bout, out, kc0, kc1, ke0, ke1);
}

// round 3
// speedup vs baseline: 1.1351x; 1.1351x over previous
#include <cuda_runtime.h>
#include <stdint.h>

// ProbabilisticPrediction fused kernel, R3: 8 (b,q) rows per block for 8x
// weight reuse. 128 blocks x 256 threads (one block per SM, single wave).
// Phase 1: warp w computes Gumbel-argmax (JAX threefry) for row w and gathers
// the selected f_embed row. Phase 2: fused 3-layer MLP with per-thread
// 8-row register accumulators; activations in smem (float4 LDS broadcast).

#define B_   4
#define QL_  256
#define CL_  512
#define DIM_ 128
#define YD_  16
#define R_   8

// ---------------------------------------------------------------- threefry2x32
__host__ __device__ inline void tf2x32(uint32_t k0, uint32_t k1,
                                       uint32_t c0, uint32_t c1,
                                       uint32_t& o0, uint32_t& o1) {
    uint32_t k2 = k0 ^ k1 ^ 0x1BD11BDAu;
    uint32_t x0 = c0 + k0, x1 = c1 + k1;
#define TFR(d) do { x0 += x1; x1 = (x1 << (d)) | (x1 >> (32 - (d))); x1 ^= x0; } while (0)
    TFR(13); TFR(15); TFR(26); TFR(6);   x0 += k1; x1 += k2 + 1u;
    TFR(17); TFR(29); TFR(16); TFR(24);  x0 += k2; x1 += k0 + 2u;
    TFR(13); TFR(15); TFR(26); TFR(6);   x0 += k0; x1 += k1 + 3u;
    TFR(17); TFR(29); TFR(16); TFR(24);  x0 += k1; x1 += k2 + 4u;
    TFR(13); TFR(15); TFR(26); TFR(6);   x0 += k2; x1 += k0 + 5u;
#undef TFR
    o0 = x0; o1 = x1;
}

__device__ inline uint32_t jax_bits(uint32_t k0, uint32_t k1, uint32_t j) {
    uint32_t o0, o1;
    tf2x32(k0, k1, 0u, j, o0, o1);   // partitionable: 64-bit iota (0, j)
    return o0 ^ o1;
}

__device__ inline float bits_to_unit(uint32_t b) {      // [0, 1)
    return __uint_as_float((b >> 9) | 0x3f800000u) - 1.0f;
}

// XLA ErfInv32 (Giles) -- matches jax.random.normal exactly.
__device__ inline float erfinv_xla(float x) {
    float w = -log1pf(-x * x);
    float p;
    if (w < 5.0f) {
        w -= 2.5f;
        p =            2.81022636e-08f;
        p = fmaf(p, w, 3.43273939e-07f);
        p = fmaf(p, w, -3.5233877e-06f);
        p = fmaf(p, w, -4.39150654e-06f);
        p = fmaf(p, w, 0.00021858087f);
        p = fmaf(p, w, -0.00125372503f);
        p = fmaf(p, w, -0.00417768164f);
        p = fmaf(p, w, 0.246640727f);
        p = fmaf(p, w, 1.50140941f);
    } else {
        w = sqrtf(w) - 3.0f;
        p =            -0.000200214257f;
        p = fmaf(p, w, 0.000100950558f);
        p = fmaf(p, w, 0.00134934322f);
        p = fmaf(p, w, -0.00367342844f);
        p = fmaf(p, w, 0.00573950773f);
        p = fmaf(p, w, -0.0076224613f);
        p = fmaf(p, w, 0.00943887047f);
        p = fmaf(p, w, 1.00167406f);
        p = fmaf(p, w, 2.83297682f);
    }
    return p * x;
}

// ---------------------------------------------------------------------- kernel
__global__ __launch_bounds__(256)
void pp_fused_kernel(const float* __restrict__ q,
                     const float* __restrict__ f_embed,
                     const float* __restrict__ att_logits,
                     const float* __restrict__ W1q,
                     const float* __restrict__ W1f,
                     const float* __restrict__ b1,
                     const float* __restrict__ W2,
                     const float* __restrict__ b2,
                     const float* __restrict__ Wout,
                     const float* __restrict__ bout,
                     float* __restrict__ out,
                     uint32_t kc0, uint32_t kc1,
                     uint32_t ke0, uint32_t ke1)
{
    const int t   = threadIdx.x;         // 0..255
    const int w   = t >> 5;              // warp 0..7 == row r
    const int ln  = t & 31;
    const int bq0 = blockIdx.x * R_;
    const int b   = bq0 >> 8;            // all R_ rows share b (8 | 256)

    __shared__ float sQ[R_ * DIM_];          // q rows (later reused as h2)
    __shared__ float sF[R_ * DIM_];          // selected f rows
    __shared__ float sH[R_ * DIM_];          // h1
    __shared__ float sPar[2 * R_ * DIM_];    // partial sums (d-halves)
    __shared__ float sWout[DIM_ * 2 * YD_];  // Wout staged
    __shared__ float sO[R_ * 2 * YD_];       // layer-3 outputs

    // -------- cooperative loads (issued early; hidden under phase-1 ALU) ----
    {
        float4* dq = (float4*)sQ;
        const float4* srq = (const float4*)(q + (size_t)bq0 * DIM_);
        dq[t] = srq[t];                                   // 256 f4 = 1024 floats
        float4* dw = (float4*)sWout;
        const float4* srw = (const float4*)Wout;
#pragma unroll
        for (int k = 0; k < 4; ++k) dw[t + k * 256] = srw[t + k * 256];
    }

    // -------- Phase 1: per-warp Gumbel-argmax for row w ---------------------
    const int bq = bq0 + w;
    {
        const float TINY = 1.17549435e-38f;
        float best = -__int_as_float(0x7f800000);
        int bi = 0;
        const float* lrow = att_logits + (size_t)bq * CL_;
#pragma unroll 4
        for (int i = 0; i < CL_ / 32; ++i) {
            int c = ln + i * 32;
            uint32_t j = (uint32_t)bq * (uint32_t)CL_ + (uint32_t)c;
            float u = bits_to_unit(jax_bits(kc0, kc1, j));
            u = fmaxf(TINY, u * (1.0f - TINY) + TINY);
            float g = -logf(-logf(u));
            float v = g + lrow[c];
            if (v > best || (v == best && c < bi)) { best = v; bi = c; }
        }
#pragma unroll
        for (int off = 16; off; off >>= 1) {
            float v2 = __shfl_xor_sync(0xffffffffu, best, off);
            int   i2 = __shfl_xor_sync(0xffffffffu, bi,   off);
            if (v2 > best || (v2 == best && i2 < bi)) { best = v2; bi = i2; }
        }
        // bi is lane-uniform: warp-local f-row gather, no block sync needed
        const float4* fsrc = (const float4*)(f_embed + ((size_t)b * CL_ + bi) * DIM_);
        ((float4*)(sF + w * DIM_))[ln] = fsrc[ln];
    }
    __syncthreads();

    // -------- Phase 2: fused MLP, 8 rows per thread -------------------------
    const int c    = t & 127;            // output column
    const int half = t >> 7;             // d-half 0/1
    const int dbase = half * 64;

    // Layer 1: h = relu(q@W1q + f@W1f + b1)
    {
        float acc[R_];
#pragma unroll
        for (int r = 0; r < R_; ++r) acc[r] = 0.f;
        const float* wq = W1q + c;
        const float* wf = W1f + c;
#pragma unroll 4
        for (int i = 0; i < 16; ++i) {
            const int d = dbase + i * 4;
            float wq0 = wq[(d + 0) * DIM_], wq1 = wq[(d + 1) * DIM_];
            float wq2 = wq[(d + 2) * DIM_], wq3 = wq[(d + 3) * DIM_];
            float wf0 = wf[(d + 0) * DIM_], wf1 = wf[(d + 1) * DIM_];
            float wf2 = wf[(d + 2) * DIM_], wf3 = wf[(d + 3) * DIM_];
#pragma unroll
            for (int r = 0; r < R_; ++r) {
                float4 qv = ((const float4*)sQ)[r * 32 + (d >> 2)];
                float4 fv = ((const float4*)sF)[r * 32 + (d >> 2)];
                acc[r] = fmaf(qv.x, wq0, acc[r]); acc[r] = fmaf(qv.y, wq1, acc[r]);
                acc[r] = fmaf(qv.z, wq2, acc[r]); acc[r] = fmaf(qv.w, wq3, acc[r]);
                acc[r] = fmaf(fv.x, wf0, acc[r]); acc[r] = fmaf(fv.y, wf1, acc[r]);
                acc[r] = fmaf(fv.z, wf2, acc[r]); acc[r] = fmaf(fv.w, wf3, acc[r]);
            }
        }
#pragma unroll
        for (int r = 0; r < R_; ++r) sPar[half * 1024 + r * DIM_ + c] = acc[r];
    }
    __syncthreads();
#pragma unroll
    for (int k = 0; k < 4; ++k) {
        int i = t + k * 256;
        sH[i] = fmaxf(sPar[i] + sPar[1024 + i] + b1[i & 127], 0.f);
    }
    __syncthreads();

    // Layer 2: h2 = relu(h@W2 + b2)
    {
        float acc[R_];
#pragma unroll
        for (int r = 0; r < R_; ++r) acc[r] = 0.f;
        const float* w2 = W2 + c;
#pragma unroll 4
        for (int i = 0; i < 16; ++i) {
            const int d = dbase + i * 4;
            float w0 = w2[(d + 0) * DIM_], w1 = w2[(d + 1) * DIM_];
            float w2v = w2[(d + 2) * DIM_], w3 = w2[(d + 3) * DIM_];
#pragma unroll
            for (int r = 0; r < R_; ++r) {
                float4 hv = ((const float4*)sH)[r * 32 + (d >> 2)];
                acc[r] = fmaf(hv.x, w0,  acc[r]); acc[r] = fmaf(hv.y, w1, acc[r]);
                acc[r] = fmaf(hv.z, w2v, acc[r]); acc[r] = fmaf(hv.w, w3, acc[r]);
            }
        }
#pragma unroll
        for (int r = 0; r < R_; ++r) sPar[half * 1024 + r * DIM_ + c] = acc[r];
    }
    __syncthreads();
#pragma unroll
    for (int k = 0; k < 4; ++k) {
        int i = t + k * 256;
        sQ[i] = fmaxf(sPar[i] + sPar[1024 + i] + b2[i & 127], 0.f);  // sQ := h2
    }
    __syncthreads();

    // Layer 3: out = h2@Wout + bout  (one output per thread: r=w, o=ln)
    {
        const int o = ln;
        float a0 = 0.f, a1 = 0.f;
#pragma unroll 8
        for (int d4 = 0; d4 < 32; ++d4) {
            float4 hv = ((const float4*)sQ)[w * 32 + d4];
            a0 = fmaf(hv.x, sWout[(d4 * 4 + 0) * 32 + o], a0);
            a1 = fmaf(hv.y, sWout[(d4 * 4 + 1) * 32 + o], a1);
            a0 = fmaf(hv.z, sWout[(d4 * 4 + 2) * 32 + o], a0);
            a1 = fmaf(hv.w, sWout[(d4 * 4 + 3) * 32 + o], a1);
        }
        sO[w * 32 + o] = a0 + a1 + bout[o];
    }
    __syncthreads();

    // -------- Sample: y = mu + softplus(max(-15,s)) * eps -------------------
    if (t < R_ * YD_) {                        // 128 threads
        const int rr = t >> 4, y = t & 15;
        uint32_t m = (uint32_t)(bq0 + rr) * (uint32_t)YD_ + (uint32_t)y;
        float u = bits_to_unit(jax_bits(ke0, ke1, m));
        const float lo = -0.99999994f;
        float x = fmaxf(lo, u * (1.0f - lo) + lo);
        float eps = 1.41421356237f * erfinv_xla(x);
        float s = fmaxf(-15.0f, sO[rr * 32 + YD_ + y]);
        float sigma = fmaxf(s, 0.0f) + log1pf(expf(-fabsf(s)));
        out[(size_t)bq0 * YD_ + t] = fmaf(sigma, eps, sO[rr * 32 + y]);
    }
}

// ---------------------------------------------------------------------- launch
extern "C" void kernel_launch(void* const* d_in, const int* in_sizes, int n_in,
                              void* d_out, int out_size) {
    const float* q     = (const float*)d_in[0];
    const float* f_emb = (const float*)d_in[1];
    const float* alog  = (const float*)d_in[2];
    const float* W1q   = (const float*)d_in[3];
    const float* W1f   = (const float*)d_in[4];
    const float* b1    = (const float*)d_in[5];
    const float* W2    = (const float*)d_in[6];
    const float* b2    = (const float*)d_in[7];
    const float* Wout  = (const float*)d_in[8];
    const float* bout  = (const float*)d_in[9];
    float* out = (float*)d_out;

    // split(jax.random.key(1), 2), partitionable: subkey_i = tf(key, (0, i))
    uint32_t kc0, kc1, ke0, ke1;
    tf2x32(0u, 1u, 0u, 0u, kc0, kc1);
    tf2x32(0u, 1u, 0u, 1u, ke0, ke1);

    pp_fused_kernel<<<(B_ * QL_) / R_, 256>>>(q, f_emb, alog, W1q, W1f, b1,
                                              W2, b2, Wout, bout, out,
                                              kc0, kc1, ke0, ke1);
}

// round 4
// speedup vs baseline: 1.4640x; 1.2898x over previous
#include <cuda_runtime.h>
#include <stdint.h>

// ProbabilisticPrediction fused kernel, R4: 8 rows/block, 1024 threads/block
// (32 warps/SM, occ 50%) to hide L2/LDS latency. d-dimension split 8-way with
// smem partial reduction. Gumbel-argmax (JAX threefry partitionable) selects
// the single mixture component per (b,q); MLP evaluated only there.

#define B_   4
#define QL_  256
#define CL_  512
#define DIM_ 128
#define YD_  16
#define R_   8

// ---------------------------------------------------------------- threefry2x32
__host__ __device__ inline void tf2x32(uint32_t k0, uint32_t k1,
                                       uint32_t c0, uint32_t c1,
                                       uint32_t& o0, uint32_t& o1) {
    uint32_t k2 = k0 ^ k1 ^ 0x1BD11BDAu;
    uint32_t x0 = c0 + k0, x1 = c1 + k1;
#define TFR(d) do { x0 += x1; x1 = (x1 << (d)) | (x1 >> (32 - (d))); x1 ^= x0; } while (0)
    TFR(13); TFR(15); TFR(26); TFR(6);   x0 += k1; x1 += k2 + 1u;
    TFR(17); TFR(29); TFR(16); TFR(24);  x0 += k2; x1 += k0 + 2u;
    TFR(13); TFR(15); TFR(26); TFR(6);   x0 += k0; x1 += k1 + 3u;
    TFR(17); TFR(29); TFR(16); TFR(24);  x0 += k1; x1 += k2 + 4u;
    TFR(13); TFR(15); TFR(26); TFR(6);   x0 += k2; x1 += k0 + 5u;
#undef TFR
    o0 = x0; o1 = x1;
}

__device__ inline uint32_t jax_bits(uint32_t k0, uint32_t k1, uint32_t j) {
    uint32_t o0, o1;
    tf2x32(k0, k1, 0u, j, o0, o1);   // partitionable: 64-bit iota (0, j)
    return o0 ^ o1;
}

__device__ inline float bits_to_unit(uint32_t b) {      // [0, 1)
    return __uint_as_float((b >> 9) | 0x3f800000u) - 1.0f;
}

// XLA ErfInv32 (Giles) -- matches jax.random.normal exactly.
__device__ inline float erfinv_xla(float x) {
    float w = -log1pf(-x * x);
    float p;
    if (w < 5.0f) {
        w -= 2.5f;
        p =            2.81022636e-08f;
        p = fmaf(p, w, 3.43273939e-07f);
        p = fmaf(p, w, -3.5233877e-06f);
        p = fmaf(p, w, -4.39150654e-06f);
        p = fmaf(p, w, 0.00021858087f);
        p = fmaf(p, w, -0.00125372503f);
        p = fmaf(p, w, -0.00417768164f);
        p = fmaf(p, w, 0.246640727f);
        p = fmaf(p, w, 1.50140941f);
    } else {
        w = sqrtf(w) - 3.0f;
        p =            -0.000200214257f;
        p = fmaf(p, w, 0.000100950558f);
        p = fmaf(p, w, 0.00134934322f);
        p = fmaf(p, w, -0.00367342844f);
        p = fmaf(p, w, 0.00573950773f);
        p = fmaf(p, w, -0.0076224613f);
        p = fmaf(p, w, 0.00943887047f);
        p = fmaf(p, w, 1.00167406f);
        p = fmaf(p, w, 2.83297682f);
    }
    return p * x;
}

// ---------------------------------------------------------------------- kernel
__global__ __launch_bounds__(1024, 1)
void pp_fused_kernel(const float* __restrict__ q,
                     const float* __restrict__ f_embed,
                     const float* __restrict__ att_logits,
                     const float* __restrict__ W1q,
                     const float* __restrict__ W1f,
                     const float* __restrict__ b1,
                     const float* __restrict__ W2,
                     const float* __restrict__ b2,
                     const float* __restrict__ Wout,
                     const float* __restrict__ bout,
                     float* __restrict__ out,
                     uint32_t kc0, uint32_t kc1,
                     uint32_t ke0, uint32_t ke1)
{
    const int t   = threadIdx.x;         // 0..1023
    const int w   = t >> 5;              // warp 0..31
    const int ln  = t & 31;
    const int bq0 = blockIdx.x * R_;
    const int b   = bq0 >> 8;            // all R_ rows share b (8 | 256)

    __shared__ float sQ[R_ * DIM_];      // q rows; later h2
    __shared__ float sF[R_ * DIM_];      // selected f rows
    __shared__ float sH[R_ * DIM_];      // h1
    __shared__ float sPar[8 * R_ * DIM_];// 8-way partials (32KB); reused L3
    __shared__ float sO[R_ * 2 * YD_];
    __shared__ float sVal[32];
    __shared__ int   sIdxW[32];
    __shared__ int   sIdxRow[R_];

    // Prefetch q rows (hidden under phase-1 ALU).
    if (t < 256)
        ((float4*)sQ)[t] = ((const float4*)(q + (size_t)bq0 * DIM_))[t];

    // -------- Phase 1: Gumbel-argmax; row r = w>>2, sub-range sub = w&3 -----
    {
        const int r = w >> 2, sub = w & 3;
        const int bq = bq0 + r;
        const float* lrow = att_logits + (size_t)bq * CL_;
        const float TINY = 1.17549435e-38f;
        float best = -__int_as_float(0x7f800000);
        int bi = 0;
#pragma unroll
        for (int i = 0; i < 4; ++i) {
            int c = sub * 128 + i * 32 + ln;
            uint32_t j = (uint32_t)bq * (uint32_t)CL_ + (uint32_t)c;
            float u = bits_to_unit(jax_bits(kc0, kc1, j));
            u = fmaxf(TINY, u * (1.0f - TINY) + TINY);
            float g = -logf(-logf(u));
            float v = g + lrow[c];
            if (v > best || (v == best && c < bi)) { best = v; bi = c; }
        }
#pragma unroll
        for (int off = 16; off; off >>= 1) {
            float v2 = __shfl_xor_sync(0xffffffffu, best, off);
            int   i2 = __shfl_xor_sync(0xffffffffu, bi,   off);
            if (v2 > best || (v2 == best && i2 < bi)) { best = v2; bi = i2; }
        }
        if (ln == 0) { sVal[w] = best; sIdxW[w] = bi; }
    }
    __syncthreads();
    if (t < R_) {
        float bv = sVal[t * 4]; int bj = sIdxW[t * 4];
#pragma unroll
        for (int k = 1; k < 4; ++k) {
            float v2 = sVal[t * 4 + k]; int i2 = sIdxW[t * 4 + k];
            if (v2 > bv || (v2 == bv && i2 < bj)) { bv = v2; bj = i2; }
        }
        sIdxRow[t] = bj;
    }
    __syncthreads();
    if (t < 256) {   // gather selected f rows
        const int rr = t >> 5;
        ((float4*)(sF + rr * DIM_))[t & 31] =
            ((const float4*)(f_embed + ((size_t)b * CL_ + sIdxRow[rr]) * DIM_))[t & 31];
    }
    __syncthreads();

    const int c   = t & 127;             // output column
    const int oct = t >> 7;              // d-octant 0..7 (16 d's each)

    // -------- Layer 1: h = relu(q@W1q + f@W1f + b1) -------------------------
    {
        float acc[R_];
#pragma unroll
        for (int r = 0; r < R_; ++r) acc[r] = 0.f;
        const float* wq = W1q + c;
        const float* wf = W1f + c;
#pragma unroll
        for (int i = 0; i < 4; ++i) {
            const int d = oct * 16 + i * 4;
            float wq0 = wq[(d + 0) * DIM_], wq1 = wq[(d + 1) * DIM_];
            float wq2 = wq[(d + 2) * DIM_], wq3 = wq[(d + 3) * DIM_];
            float wf0 = wf[(d + 0) * DIM_], wf1 = wf[(d + 1) * DIM_];
            float wf2 = wf[(d + 2) * DIM_], wf3 = wf[(d + 3) * DIM_];
#pragma unroll
            for (int r = 0; r < R_; ++r) {
                float4 qv = ((const float4*)sQ)[r * 32 + (d >> 2)];
                float4 fv = ((const float4*)sF)[r * 32 + (d >> 2)];
                acc[r] = fmaf(qv.x, wq0, acc[r]); acc[r] = fmaf(qv.y, wq1, acc[r]);
                acc[r] = fmaf(qv.z, wq2, acc[r]); acc[r] = fmaf(qv.w, wq3, acc[r]);
                acc[r] = fmaf(fv.x, wf0, acc[r]); acc[r] = fmaf(fv.y, wf1, acc[r]);
                acc[r] = fmaf(fv.z, wf2, acc[r]); acc[r] = fmaf(fv.w, wf3, acc[r]);
            }
        }
#pragma unroll
        for (int r = 0; r < R_; ++r) sPar[oct * 1024 + r * DIM_ + c] = acc[r];
    }
    __syncthreads();
    {
        float s = 0.f;
#pragma unroll
        for (int k = 0; k < 8; ++k) s += sPar[k * 1024 + t];
        sH[t] = fmaxf(s + b1[c], 0.f);
    }
    __syncthreads();

    // -------- Layer 2: h2 = relu(h@W2 + b2) ---------------------------------
    {
        float acc[R_];
#pragma unroll
        for (int r = 0; r < R_; ++r) acc[r] = 0.f;
        const float* w2 = W2 + c;
#pragma unroll
        for (int i = 0; i < 4; ++i) {
            const int d = oct * 16 + i * 4;
            float w0 = w2[(d + 0) * DIM_], w1 = w2[(d + 1) * DIM_];
            float w2v = w2[(d + 2) * DIM_], w3 = w2[(d + 3) * DIM_];
#pragma unroll
            for (int r = 0; r < R_; ++r) {
                float4 hv = ((const float4*)sH)[r * 32 + (d >> 2)];
                acc[r] = fmaf(hv.x, w0,  acc[r]); acc[r] = fmaf(hv.y, w1, acc[r]);
                acc[r] = fmaf(hv.z, w2v, acc[r]); acc[r] = fmaf(hv.w, w3, acc[r]);
            }
        }
#pragma unroll
        for (int r = 0; r < R_; ++r) sPar[oct * 1024 + r * DIM_ + c] = acc[r];
    }
    __syncthreads();
    {
        float s = 0.f;
#pragma unroll
        for (int k = 0; k < 8; ++k) s += sPar[k * 1024 + t];
        sQ[t] = fmaxf(s + b2[c], 0.f);   // sQ := h2
    }
    __syncthreads();

    // -------- Layer 3: out = h2@Wout + bout  (4-way d-split) ----------------
    {
        const int p  = t >> 8;           // 0..3, d in [p*32, p*32+32)
        const int rr = (t >> 5) & 7;
        const int o  = ln;
        float a0 = 0.f, a1 = 0.f;
#pragma unroll
        for (int d4 = 0; d4 < 8; ++d4) {
            const int d = p * 32 + d4 * 4;
            float4 hv = ((const float4*)sQ)[rr * 32 + (d >> 2)];
            a0 = fmaf(hv.x, Wout[(d + 0) * 32 + o], a0);
            a1 = fmaf(hv.y, Wout[(d + 1) * 32 + o], a1);
            a0 = fmaf(hv.z, Wout[(d + 2) * 32 + o], a0);
            a1 = fmaf(hv.w, Wout[(d + 3) * 32 + o], a1);
        }
        sPar[p * 256 + rr * 32 + o] = a0 + a1;
    }
    __syncthreads();
    if (t < 256) {
        sO[t] = sPar[t] + sPar[256 + t] + sPar[512 + t] + sPar[768 + t]
              + bout[t & 31];
    }
    __syncthreads();

    // -------- Sample: y = mu + softplus(max(-15,s)) * eps -------------------
    if (t < R_ * YD_) {                  // 128 threads
        const int rr = t >> 4, y = t & 15;
        uint32_t m = (uint32_t)(bq0 + rr) * (uint32_t)YD_ + (uint32_t)y;
        float u = bits_to_unit(jax_bits(ke0, ke1, m));
        const float lo = -0.99999994f;
        float x = fmaxf(lo, u * (1.0f - lo) + lo);
        float eps = 1.41421356237f * erfinv_xla(x);
        float s = fmaxf(-15.0f, sO[rr * 32 + YD_ + y]);
        float sigma = fmaxf(s, 0.0f) + log1pf(expf(-fabsf(s)));
        out[(size_t)bq0 * YD_ + t] = fmaf(sigma, eps, sO[rr * 32 + y]);
    }
}

// ---------------------------------------------------------------------- launch
extern "C" void kernel_launch(void* const* d_in, const int* in_sizes, int n_in,
                              void* d_out, int out_size) {
    const float* q     = (const float*)d_in[0];
    const float* f_emb = (const float*)d_in[1];
    const float* alog  = (const float*)d_in[2];
    const float* W1q   = (const float*)d_in[3];
    const float* W1f   = (const float*)d_in[4];
    const float* b1    = (const float*)d_in[5];
    const float* W2    = (const float*)d_in[6];
    const float* b2    = (const float*)d_in[7];
    const float* Wout  = (const float*)d_in[8];
    const float* bout  = (const float*)d_in[9];
    float* out = (float*)d_out;

    // split(jax.random.key(1), 2), partitionable: subkey_i = tf(key, (0, i))
    uint32_t kc0, kc1, ke0, ke1;
    tf2x32(0u, 1u, 0u, 0u, kc0, kc1);
    tf2x32(0u, 1u, 0u, 1u, ke0, ke1);

    pp_fused_kernel<<<(B_ * QL_) / R_, 1024>>>(q, f_emb, alog, W1q, W1f, b1,
                                               W2, b2, Wout, bout, out,
                                               kc0, kc1, ke0, ke1);
}